// round 2
// baseline (speedup 1.0000x reference)
#include <cuda_runtime.h>
#include <math.h>

// ---------------- problem constants ----------------
constexpr int B_   = 16;
constexpr int T_   = 256;
constexpr int CH_  = 16;
constexpr int CIN_ = 64;
constexpr int D_   = 512;
constexpr int H_   = 8;
constexpr int E_   = 64;
constexpr int NL_  = 2;
constexpr int M_   = 64;     // fourier modes kept
constexpr int L_   = T_ + 1; // 257
constexpr int BE_  = B_ * CH_;      // 256
constexpr int MR   = BE_ * L_;      // 65792 rows for D-wide gemms
constexpr int R_   = BE_ * D_;      // 131072 rows for fourier gemms
constexpr int K3   = 3 * CIN_;      // 192

// ---------------- scratch (device globals; no allocs allowed) ----------------
// Aliasing plan (each big buffer is BE*L*D = 33.7M floats):
//   g_q  also serves as: xcat (12.6M fl) during embedding; Ainv (16.8M fl) during fourier inverse
//   g_t  also serves as: Xr (first 8.4M fl) + Xi (next 8.4M fl) during DFT
__device__ float g_h   [(size_t)BE_ * L_ * D_];
__device__ float g_q   [(size_t)BE_ * L_ * D_];
__device__ float g_t   [(size_t)BE_ * L_ * D_];
__device__ float g_xq  [(size_t)BE_ * D_ * L_];   // also holds inverse-DFT output
__device__ float g_W2t [(size_t)D_ * K3];
__device__ float g_cosT [M_ * L_];   // cosT[m*L + l]  =  cos(2*pi*m*l/L)
__device__ float g_sinTn[M_ * L_];   // sinTn[m*L + l] = -sin(2*pi*m*l/L)
__device__ float g_Binv [L_ * 2 * M_]; // [t*128+k]: k<64 cos, k>=64 -sin
__device__ float g_z  [BE_ * D_];
__device__ float g_z2 [B_ * D_];

// ---------------- generic tiled SGEMM (NT): C[M,N] = A[M,K] * B[N,K]^T ----------------
// mode 0: C = acc + bias
// mode 1: C = acc + bias + res
// mode 2: C = gelu(acc + bias)
__global__ void k_sgemm_nt(const float* __restrict__ A, const float* __restrict__ Bm,
                           float* __restrict__ C, const float* __restrict__ bias,
                           const float* __restrict__ res,
                           int Md, int Nd, int Kd, int mode) {
    __shared__ float sA[16][64];
    __shared__ float sB[16][64];
    const int tid = threadIdx.x;
    const int tx = tid & 15;          // n direction (4 outputs)
    const int ty = tid >> 4;          // m direction (4 outputs)
    const int m0 = blockIdx.y * 64;
    const int n0 = blockIdx.x * 64;

    float acc[4][4] = {};

    for (int k0 = 0; k0 < Kd; k0 += 16) {
        #pragma unroll
        for (int idx = tid; idx < 1024; idx += 256) {
            const int r = idx >> 4;
            const int c = idx & 15;
            const int gk = k0 + c;
            const int gm = m0 + r;
            const int gn = n0 + r;
            sA[c][r] = (gm < Md && gk < Kd) ? A[(size_t)gm * Kd + gk] : 0.f;
            sB[c][r] = (gn < Nd && gk < Kd) ? Bm[(size_t)gn * Kd + gk] : 0.f;
        }
        __syncthreads();
        #pragma unroll
        for (int k = 0; k < 16; ++k) {
            const float4 a4 = *reinterpret_cast<const float4*>(&sA[k][ty * 4]);
            const float4 b4 = *reinterpret_cast<const float4*>(&sB[k][tx * 4]);
            const float av[4] = {a4.x, a4.y, a4.z, a4.w};
            const float bv[4] = {b4.x, b4.y, b4.z, b4.w};
            #pragma unroll
            for (int i = 0; i < 4; ++i)
                #pragma unroll
                for (int j = 0; j < 4; ++j)
                    acc[i][j] += av[i] * bv[j];
        }
        __syncthreads();
    }

    #pragma unroll
    for (int i = 0; i < 4; ++i) {
        const int m = m0 + ty * 4 + i;
        if (m >= Md) continue;
        #pragma unroll
        for (int j = 0; j < 4; ++j) {
            const int n = n0 + tx * 4 + j;
            if (n >= Nd) continue;
            float v = acc[i][j] + (bias ? bias[n] : 0.f);
            if (mode == 1)      v += res[(size_t)m * Nd + n];
            else if (mode == 2) v = 0.5f * v * (1.f + erff(v * 0.70710678118654752f));
            C[(size_t)m * Nd + n] = v;
        }
    }
}

// ---------------- DFT basis tables ----------------
__global__ void k_init_tables() {
    const int idx = blockIdx.x * blockDim.x + threadIdx.x;
    if (idx >= M_ * L_) return;
    const int m = idx / L_;
    const int l = idx % L_;
    const long r = ((long)m * l) % L_;
    const double ang = 6.283185307179586476925 * (double)r / (double)L_;
    g_cosT[idx]  = (float)cos(ang);
    g_sinTn[idx] = (float)(-sin(ang));
}

__global__ void k_init_binv() {
    const int idx = blockIdx.x * blockDim.x + threadIdx.x;
    if (idx >= L_ * 2 * M_) return;
    const int t = idx / (2 * M_);
    const int k = idx % (2 * M_);
    const int m = (k < M_) ? k : (k - M_);
    const long r = ((long)t * m) % L_;
    const double ang = 6.283185307179586476925 * (double)r / (double)L_;
    g_Binv[idx] = (k < M_) ? (float)cos(ang) : (float)(-sin(ang));
}

// ---------------- token embedding prep ----------------
// W2t[o, k*64+i] = tok_w[o, i, k]
__global__ void k_w2t(const float* __restrict__ tok_w) {
    const int idx = blockIdx.x * blockDim.x + threadIdx.x;
    if (idx >= D_ * K3) return;
    const int o = idx / K3;
    const int c = idx % K3;
    const int k = c / CIN_;
    const int i = c % CIN_;
    g_W2t[idx] = tok_w[(o * CIN_ + i) * 3 + k];
}

// xcat[(be,l), k*64+i] = xc[be, (l+k-1) mod L, i]   (written into aliased buffer)
__global__ void k_xcat(const float* __restrict__ x, const float* __restrict__ cls,
                       float* __restrict__ xcat) {
    const size_t idx = (size_t)blockIdx.x * blockDim.x + threadIdx.x;
    if (idx >= (size_t)BE_ * L_ * K3) return;
    const int c  = (int)(idx % K3);
    const int l  = (int)((idx / K3) % L_);
    const int be = (int)(idx / ((size_t)K3 * L_));
    const int k = c / CIN_;
    const int i = c % CIN_;
    const int ls = (l + k - 1 + L_) % L_;
    const int b  = be / CH_;
    const int ch = be % CH_;
    float v;
    if (ls == 0) v = cls[ch * CIN_ + i];
    else         v = x[(((size_t)b * T_ + (ls - 1)) * CH_ + ch) * CIN_ + i];
    xcat[idx] = v;
}

// sinusoidal positional embedding, added in place
__global__ void k_posadd() {
    const size_t idx = (size_t)blockIdx.x * blockDim.x + threadIdx.x;
    if (idx >= (size_t)BE_ * L_ * D_) return;
    const int d = (int)(idx % D_);
    const int l = (int)((idx / D_) % L_);
    const int j = d >> 1;
    const float div = expf(-(float)(2 * j) * (9.210340371976184f / (float)D_));
    const float ang = (float)l * div;
    g_h[idx] += (d & 1) ? cosf(ang) : sinf(ang);
}

// ---------------- batched transpose: in (batch, Rr, Cc) -> out (batch, Cc, Rr) ----------------
__global__ void k_transpose(const float* __restrict__ in, float* __restrict__ out, int Rr, int Cc) {
    __shared__ float tile[32][33];
    const int b  = blockIdx.z;
    const int r0 = blockIdx.y * 32;
    const int c0 = blockIdx.x * 32;
    const int x = threadIdx.x;
    const int y = threadIdx.y;
    #pragma unroll
    for (int yy = y; yy < 32; yy += 8) {
        const int r = r0 + yy, c = c0 + x;
        if (r < Rr && c < Cc) tile[yy][x] = in[((size_t)b * Rr + r) * Cc + c];
    }
    __syncthreads();
    #pragma unroll
    for (int yy = y; yy < 32; yy += 8) {
        const int c = c0 + yy, r = r0 + x;
        if (r < Rr && c < Cc) out[((size_t)b * Cc + c) * Rr + r] = tile[x][yy];
    }
}

// ---------------- complex frequency mixing (fused with inverse-DFT operand scaling) ----------
// S[be,h,o,m] = sum_i X[be,h,i,m] * (wr + i*wi)[h,i,o,m]
// Output written directly in Ainv layout: Ainv[row,m] = c_m*Re(S), Ainv[row,64+m] = c_m*Im(S)
// where row = be*512 + h*64 + o  and  c_m = (m?2:1)/257.
__global__ void k_mix(const float* __restrict__ Xr, const float* __restrict__ Xi,
                      const float* __restrict__ fwr, const float* __restrict__ fwi,
                      float* __restrict__ Ainv) {
    const int be = blockIdx.x;
    const int hh = blockIdx.y;
    __shared__ float sXr[E_ * M_];
    __shared__ float sXi[E_ * M_];
    const int tid = threadIdx.x;   // 256
    const size_t xbase = ((size_t)(be * H_ + hh)) * E_ * M_;
    for (int i = tid; i < E_ * M_; i += 256) {
        sXr[i] = Xr[xbase + i];
        sXi[i] = Xi[xbase + i];
    }
    __syncthreads();
    const int m    = tid & 63;
    const int orow = tid >> 6;     // 0..3
    const float cm = ((m == 0) ? 1.f : 2.f) / (float)L_;
    for (int oo = 0; oo < 16; ++oo) {
        const int o = oo * 4 + orow;
        const size_t wbase = ((size_t)hh * E_ * E_) * M_ + (size_t)o * M_ + m;
        float ar = 0.f, ai = 0.f;
        #pragma unroll 4
        for (int i = 0; i < E_; ++i) {
            const float xre = sXr[i * M_ + m];
            const float xim = sXi[i * M_ + m];
            const float wre = fwr[wbase + (size_t)i * (E_ * M_)];
            const float wim = fwi[wbase + (size_t)i * (E_ * M_)];
            ar += xre * wre - xim * wim;
            ai += xre * wim + xim * wre;
        }
        const size_t row = ((size_t)be * H_ + hh) * E_ + o;   // = be*512 + hh*64 + o
        Ainv[row * (2 * M_) + m]      = cm * ar;
        Ainv[row * (2 * M_) + M_ + m] = cm * ai;
    }
}

// ---------------- series_decomp residual: h[be,:,d] -= movmean_25(h[be,:,d]) (edge-replicate) ----------------
__global__ void k_movmean(float* __restrict__ hbuf) {
    const int be = blockIdx.x;
    const int d0 = blockIdx.y * 32;
    __shared__ float s[L_ * 32];   // 32.9 KB
    const int tid = threadIdx.x;   // 256
    for (int idx = tid; idx < L_ * 32; idx += 256) {
        const int l = idx >> 5, dd = idx & 31;
        s[idx] = hbuf[((size_t)be * L_ + l) * D_ + d0 + dd];
    }
    __syncthreads();
    for (int idx = tid; idx < L_ * 32; idx += 256) {
        const int l = idx >> 5, dd = idx & 31;
        float acc = 0.f;
        #pragma unroll
        for (int j = -12; j <= 12; ++j) {
            int jj = l + j;
            jj = jj < 0 ? 0 : (jj > L_ - 1 ? L_ - 1 : jj);
            acc += s[(jj << 5) + dd];
        }
        hbuf[((size_t)be * L_ + l) * D_ + d0 + dd] = s[idx] - acc * (1.f / 25.f);
    }
}

// ---------------- final LayerNorm over D + mean over L -> z[be, d] ----------------
__global__ void k_lnpool(const float* __restrict__ g, const float* __restrict__ b) {
    const int be = blockIdx.x;
    const int tid = threadIdx.x;   // 512 == D_
    __shared__ float ws[16], ws2[16];
    const int wid = tid >> 5, lane = tid & 31;
    const float gg = g[tid], bb = b[tid];
    float acc = 0.f;
    for (int l = 0; l < L_; ++l) {
        const float v = g_h[((size_t)be * L_ + l) * D_ + tid];
        float s = v, s2 = v * v;
        #pragma unroll
        for (int off = 16; off > 0; off >>= 1) {
            s  += __shfl_xor_sync(0xffffffffu, s, off);
            s2 += __shfl_xor_sync(0xffffffffu, s2, off);
        }
        if (lane == 0) { ws[wid] = s; ws2[wid] = s2; }
        __syncthreads();
        float tot = 0.f, tot2 = 0.f;
        #pragma unroll
        for (int w = 0; w < 16; ++w) { tot += ws[w]; tot2 += ws2[w]; }
        const float mu  = tot * (1.f / (float)D_);
        const float var = tot2 * (1.f / (float)D_) - mu * mu;
        const float inv = rsqrtf(var + 1e-5f);
        acc += (v - mu) * inv * gg + bb;
        __syncthreads();
    }
    g_z[(size_t)be * D_ + tid] = acc * (1.f / (float)L_);
}

// ---------------- final tiny dot ----------------
__global__ void k_dec2(const float* __restrict__ w, const float* __restrict__ bias,
                       float* __restrict__ out) {
    const int bb = blockIdx.x;
    const int tid = threadIdx.x; // 128
    float acc = 0.f;
    for (int d = tid; d < D_; d += 128) acc += g_z2[bb * D_ + d] * w[d];
    #pragma unroll
    for (int off = 16; off > 0; off >>= 1) acc += __shfl_xor_sync(0xffffffffu, acc, off);
    __shared__ float ws[4];
    if ((tid & 31) == 0) ws[tid >> 5] = acc;
    __syncthreads();
    if (tid == 0) out[bb] = ws[0] + ws[1] + ws[2] + ws[3] + bias[0];
}

// ---------------- orchestration ----------------
extern "C" void kernel_launch(void* const* d_in, const int* in_sizes, int n_in,
                              void* d_out, int out_size) {
    const float* x     = (const float*)d_in[0];
    const float* cls   = (const float*)d_in[3];
    const float* tok_w = (const float*)d_in[4];
    const float* wq    = (const float*)d_in[5];
    const float* bq    = (const float*)d_in[6];
    const float* wo    = (const float*)d_in[7];
    const float* bo    = (const float*)d_in[8];
    const float* c1w   = (const float*)d_in[9];
    const float* c2w   = (const float*)d_in[10];
    const float* fwr   = (const float*)d_in[11];
    const float* fwi   = (const float*)d_in[12];
    const float* ng    = (const float*)d_in[13];
    const float* nb    = (const float*)d_in[14];
    const float* d1w   = (const float*)d_in[15];
    const float* d1b   = (const float*)d_in[16];
    const float* d2w   = (const float*)d_in[17];
    const float* d2b   = (const float*)d_in[18];
    float* out = (float*)d_out;

    float *ph, *pq, *pt, *pxq, *pW2t, *pcosT, *psinTn, *pBinv, *pz, *pz2;
    cudaGetSymbolAddress((void**)&ph,    g_h);
    cudaGetSymbolAddress((void**)&pq,    g_q);
    cudaGetSymbolAddress((void**)&pt,    g_t);
    cudaGetSymbolAddress((void**)&pxq,   g_xq);
    cudaGetSymbolAddress((void**)&pW2t,  g_W2t);
    cudaGetSymbolAddress((void**)&pcosT, g_cosT);
    cudaGetSymbolAddress((void**)&psinTn,g_sinTn);
    cudaGetSymbolAddress((void**)&pBinv, g_Binv);
    cudaGetSymbolAddress((void**)&pz,    g_z);
    cudaGetSymbolAddress((void**)&pz2,   g_z2);

    // aliases into the big buffers
    float* pxcat = pq;                 // BE*L*K3 fits in g_q
    float* pXr   = pt;                 // R_*M_ floats
    float* pXi   = pt + (size_t)R_ * M_;
    float* pAinv = pq;                 // R_*2M floats fits in g_q (q is dead after transpose)

    const dim3 gemmBig((D_ + 63) / 64, (MR + 63) / 64);   // (8, 1028)
    const dim3 gemmDft(1, (R_ + 63) / 64);                // (1, 2048)
    const dim3 gemmInv((L_ + 63) / 64, (R_ + 63) / 64);   // (5, 2048)

    // basis tables
    k_init_tables<<<(M_ * L_ + 255) / 256, 256>>>();
    k_init_binv  <<<(L_ * 2 * M_ + 255) / 256, 256>>>();

    // embedding
    k_w2t <<<(D_ * K3 + 255) / 256, 256>>>(tok_w);
    k_xcat<<<(int)(((size_t)BE_ * L_ * K3 + 255) / 256), 256>>>(x, cls, pxcat);
    k_sgemm_nt<<<gemmBig, 256>>>(pxcat, pW2t, ph, nullptr, nullptr, MR, D_, K3, 0);
    k_posadd<<<(int)(((size_t)BE_ * L_ * D_ + 255) / 256), 256>>>();

    for (int l = 0; l < NL_; ++l) {
        const float* wql = wq + (size_t)l * D_ * D_;
        const float* bql = bq + (size_t)l * D_;
        const float* wol = wo + (size_t)l * D_ * D_;
        const float* bol = bo + (size_t)l * D_;
        const float* c1l = c1w + (size_t)l * D_ * D_;
        const float* c2l = c2w + (size_t)l * D_ * D_;

        // q = h @ wq^T + bq
        k_sgemm_nt<<<gemmBig, 256>>>(ph, wql, pq, bql, nullptr, MR, D_, D_, 0);
        // xq[be,d,l] = q[be,l,d]
        k_transpose<<<dim3((D_ + 31) / 32, (L_ + 31) / 32, BE_), dim3(32, 8)>>>(pq, pxq, L_, D_);
        // DFT (modes 0..63): Xr = xq @ cosT^T, Xi = xq @ (-sinT)^T
        k_sgemm_nt<<<gemmDft, 256>>>(pxq, pcosT,  pXr, nullptr, nullptr, R_, M_, L_, 0);
        k_sgemm_nt<<<gemmDft, 256>>>(pxq, psinTn, pXi, nullptr, nullptr, R_, M_, L_, 0);
        // complex mix with learned fourier weights; writes scaled Ainv directly (q is dead now)
        k_mix<<<dim3(BE_, H_), 256>>>(pXr, pXi, fwr, fwi, pAinv);
        // inverse rDFT -> (BE, D, L) flat, which IS the reference's raw reshape to (BE*L, D)
        k_sgemm_nt<<<gemmInv, 256>>>(pAinv, pBinv, pxq, nullptr, nullptr, R_, L_, 2 * M_, 0);
        // h = h + a @ wo^T + bo
        k_sgemm_nt<<<gemmBig, 256>>>(pxq, wol, ph, bol, ph, MR, D_, D_, 1);
        // decomp1
        k_movmean<<<dim3(BE_, D_ / 32), 256>>>(ph);
        // FFN: t = gelu(h @ conv1^T); h = h + t @ conv2^T
        k_sgemm_nt<<<gemmBig, 256>>>(ph, c1l, pt, nullptr, nullptr, MR, D_, D_, 2);
        k_sgemm_nt<<<gemmBig, 256>>>(pt, c2l, ph, nullptr, ph, MR, D_, D_, 1);
        // decomp2
        k_movmean<<<dim3(BE_, D_ / 32), 256>>>(ph);
    }

    // LayerNorm + mean-pool over L -> z (BE, D) == (B, CH*D) flat
    k_lnpool<<<BE_, 512>>>(ng, nb);
    // z2 = gelu(z @ dec1^T + b1)
    k_sgemm_nt<<<dim3((D_ + 63) / 64, (B_ + 63) / 64), 256>>>(pz, d1w, pz2, d1b, nullptr, B_, D_, CH_ * D_, 2);
    // out = z2 @ dec2^T + b2
    k_dec2<<<B_, 128>>>(d2w, d2b, out);
}

// round 3
// speedup vs baseline: 2.4697x; 2.4697x over previous
#include <cuda_runtime.h>
#include <math.h>

// ---------------- problem constants ----------------
constexpr int B_   = 16;
constexpr int T_   = 256;
constexpr int CH_  = 16;
constexpr int CIN_ = 64;
constexpr int D_   = 512;
constexpr int H_   = 8;
constexpr int E_   = 64;
constexpr int NL_  = 2;
constexpr int M_   = 64;     // fourier modes kept
constexpr int L_   = T_ + 1; // 257
constexpr int LP_  = 264;    // L padded to multiple of 8 for GEMM K
constexpr int BE_  = B_ * CH_;      // 256
constexpr int MR   = BE_ * L_;      // 65792 rows for D-wide gemms (514*128)
constexpr int R_   = BE_ * D_;      // 131072 rows for fourier gemms (1024*128)
constexpr int K3   = 3 * CIN_;      // 192

// ---------------- scratch (device globals; no allocs allowed) ----------------
__device__ float g_h   [(size_t)BE_ * L_ * D_];
__device__ float g_q   [(size_t)BE_ * L_ * D_];   // also: xcat; X (DFT output R x 128)
__device__ float g_t   [(size_t)BE_ * L_ * D_];   // FFN temp; also: Ainv (R x 128)
__device__ float g_xq  [(size_t)BE_ * D_ * L_];   // inverse-DFT output (tight, R x 257 flat)
__device__ float g_xqp [(size_t)BE_ * D_ * LP_];  // padded transpose for DFT GEMM
__device__ float g_W2t [(size_t)D_ * K3];
__device__ float g_cs  [128 * LP_];               // stacked [cos; -sin] basis, K-padded
__device__ float g_Binv[L_ * 2 * M_];             // [t*128+k]: k<64 cos, k>=64 -sin
__device__ float g_z  [BE_ * D_];
__device__ float g_z2 [B_ * D_];

// ================= fast SGEMM: C[M,N] = A[M,K] @ B[N,K]^T =================
// Requirements: Md % 128 == 0, Kd % 8 == 0. Nd arbitrary (guarded).
// mode 0: C = acc + bias ; mode 1: += res ; mode 2: gelu(acc + bias)
__global__ __launch_bounds__(256, 2)
void k_gemm128(const float* __restrict__ A, const float* __restrict__ Bm,
               float* __restrict__ C, const float* __restrict__ bias,
               const float* __restrict__ res,
               int Nd, int Kd, int mode) {
    __shared__ float sA[2][8][128];
    __shared__ float sB[2][8][128];
    const int tid = threadIdx.x;
    const int m0 = blockIdx.y * 128;
    const int n0 = blockIdx.x * 128;

    const int lrow = tid >> 1;        // 0..127
    const int lcol = (tid & 1) * 4;   // 0 or 4
    const int tx = tid & 15;
    const int ty = tid >> 4;

    const float* Aptr = A + (size_t)(m0 + lrow) * Kd + lcol;
    const bool bvalid = (n0 + lrow) < Nd;
    const float* Bptr = Bm + (size_t)(n0 + lrow) * Kd + lcol;

    float acc[8][8] = {};

    // prologue: stage 0
    {
        const float4 a = *reinterpret_cast<const float4*>(Aptr);
        float4 b = make_float4(0.f, 0.f, 0.f, 0.f);
        if (bvalid) b = *reinterpret_cast<const float4*>(Bptr);
        sA[0][lcol + 0][lrow] = a.x; sA[0][lcol + 1][lrow] = a.y;
        sA[0][lcol + 2][lrow] = a.z; sA[0][lcol + 3][lrow] = a.w;
        sB[0][lcol + 0][lrow] = b.x; sB[0][lcol + 1][lrow] = b.y;
        sB[0][lcol + 2][lrow] = b.z; sB[0][lcol + 3][lrow] = b.w;
    }
    __syncthreads();

    const int nstages = Kd >> 3;
    int buf = 0;

    #define COMPUTE_STAGE(BUF)                                                     \
        _Pragma("unroll")                                                          \
        for (int k = 0; k < 8; ++k) {                                              \
            const float4 a0 = *reinterpret_cast<const float4*>(&sA[BUF][k][ty * 4]);      \
            const float4 a1 = *reinterpret_cast<const float4*>(&sA[BUF][k][64 + ty * 4]); \
            const float4 b0 = *reinterpret_cast<const float4*>(&sB[BUF][k][tx * 4]);      \
            const float4 b1 = *reinterpret_cast<const float4*>(&sB[BUF][k][64 + tx * 4]); \
            const float av[8] = {a0.x, a0.y, a0.z, a0.w, a1.x, a1.y, a1.z, a1.w};  \
            const float bv[8] = {b0.x, b0.y, b0.z, b0.w, b1.x, b1.y, b1.z, b1.w};  \
            _Pragma("unroll")                                                      \
            for (int i = 0; i < 8; ++i)                                            \
                _Pragma("unroll")                                                  \
                for (int j = 0; j < 8; ++j)                                        \
                    acc[i][j] += av[i] * bv[j];                                    \
        }

    for (int s = 1; s < nstages; ++s) {
        const float4 a = *reinterpret_cast<const float4*>(Aptr + (size_t)s * 8);
        float4 b = make_float4(0.f, 0.f, 0.f, 0.f);
        if (bvalid) b = *reinterpret_cast<const float4*>(Bptr + (size_t)s * 8);

        COMPUTE_STAGE(buf)

        const int nb = buf ^ 1;
        sA[nb][lcol + 0][lrow] = a.x; sA[nb][lcol + 1][lrow] = a.y;
        sA[nb][lcol + 2][lrow] = a.z; sA[nb][lcol + 3][lrow] = a.w;
        sB[nb][lcol + 0][lrow] = b.x; sB[nb][lcol + 1][lrow] = b.y;
        sB[nb][lcol + 2][lrow] = b.z; sB[nb][lcol + 3][lrow] = b.w;
        __syncthreads();
        buf = nb;
    }
    COMPUTE_STAGE(buf)
    #undef COMPUTE_STAGE

    // epilogue
    int mi[8];
    #pragma unroll
    for (int i = 0; i < 8; ++i) mi[i] = m0 + ((i < 4) ? (ty * 4 + i) : (64 + ty * 4 + i - 4));
    float bb[8];
    #pragma unroll
    for (int j = 0; j < 8; ++j) {
        const int n = n0 + ((j < 4) ? (tx * 4 + j) : (64 + tx * 4 + j - 4));
        bb[j] = (bias != nullptr && n < Nd) ? bias[n] : 0.f;
    }

    if ((Nd & 3) == 0 && n0 + 128 <= Nd) {
        #pragma unroll
        for (int i = 0; i < 8; ++i) {
            float* Crow = C + (size_t)mi[i] * Nd;
            const float* Rrow = res ? res + (size_t)mi[i] * Nd : nullptr;
            #pragma unroll
            for (int jb = 0; jb < 2; ++jb) {
                const int n = n0 + jb * 64 + tx * 4;
                float v[4];
                #pragma unroll
                for (int j = 0; j < 4; ++j) v[j] = acc[i][jb * 4 + j] + bb[jb * 4 + j];
                if (mode == 1) {
                    const float4 r = *reinterpret_cast<const float4*>(Rrow + n);
                    v[0] += r.x; v[1] += r.y; v[2] += r.z; v[3] += r.w;
                } else if (mode == 2) {
                    #pragma unroll
                    for (int j = 0; j < 4; ++j)
                        v[j] = 0.5f * v[j] * (1.f + erff(v[j] * 0.70710678118654752f));
                }
                float4 o; o.x = v[0]; o.y = v[1]; o.z = v[2]; o.w = v[3];
                *reinterpret_cast<float4*>(Crow + n) = o;
            }
        }
    } else {
        #pragma unroll
        for (int i = 0; i < 8; ++i) {
            float* Crow = C + (size_t)mi[i] * Nd;
            const float* Rrow = res ? res + (size_t)mi[i] * Nd : nullptr;
            #pragma unroll
            for (int j = 0; j < 8; ++j) {
                const int n = n0 + ((j < 4) ? (tx * 4 + j) : (64 + tx * 4 + j - 4));
                if (n >= Nd) continue;
                float v = acc[i][j] + bb[j];
                if (mode == 1)      v += Rrow[n];
                else if (mode == 2) v = 0.5f * v * (1.f + erff(v * 0.70710678118654752f));
                Crow[n] = v;
            }
        }
    }
}

// ---------------- DFT basis tables ----------------
__global__ void k_init_cs() {
    const int idx = blockIdx.x * blockDim.x + threadIdx.x;
    if (idx >= 128 * LP_) return;
    const int n = idx / LP_;
    const int l = idx % LP_;
    float v = 0.f;
    if (l < L_) {
        const int m = (n < M_) ? n : (n - M_);
        const long r = ((long)m * l) % L_;
        const double ang = 6.283185307179586476925 * (double)r / (double)L_;
        v = (n < M_) ? (float)cos(ang) : (float)(-sin(ang));
    }
    g_cs[idx] = v;
}

__global__ void k_init_binv() {
    const int idx = blockIdx.x * blockDim.x + threadIdx.x;
    if (idx >= L_ * 2 * M_) return;
    const int t = idx / (2 * M_);
    const int k = idx % (2 * M_);
    const int m = (k < M_) ? k : (k - M_);
    const long r = ((long)t * m) % L_;
    const double ang = 6.283185307179586476925 * (double)r / (double)L_;
    g_Binv[idx] = (k < M_) ? (float)cos(ang) : (float)(-sin(ang));
}

// zero the K-pad region of g_xqp (columns 257..263 of each row)
__global__ void k_padzero() {
    const int idx = blockIdx.x * blockDim.x + threadIdx.x;
    const int nrows = BE_ * D_;
    if (idx >= nrows * (LP_ - L_)) return;
    const int row = idx / (LP_ - L_);
    const int c   = idx % (LP_ - L_);
    g_xqp[(size_t)row * LP_ + L_ + c] = 0.f;
}

// ---------------- token embedding prep ----------------
__global__ void k_w2t(const float* __restrict__ tok_w) {
    const int idx = blockIdx.x * blockDim.x + threadIdx.x;
    if (idx >= D_ * K3) return;
    const int o = idx / K3;
    const int c = idx % K3;
    const int k = c / CIN_;
    const int i = c % CIN_;
    g_W2t[idx] = tok_w[(o * CIN_ + i) * 3 + k];
}

__global__ void k_xcat(const float* __restrict__ x, const float* __restrict__ cls,
                       float* __restrict__ xcat) {
    const size_t idx = (size_t)blockIdx.x * blockDim.x + threadIdx.x;
    if (idx >= (size_t)BE_ * L_ * K3) return;
    const int c  = (int)(idx % K3);
    const int l  = (int)((idx / K3) % L_);
    const int be = (int)(idx / ((size_t)K3 * L_));
    const int k = c / CIN_;
    const int i = c % CIN_;
    const int ls = (l + k - 1 + L_) % L_;
    const int b  = be / CH_;
    const int ch = be % CH_;
    float v;
    if (ls == 0) v = cls[ch * CIN_ + i];
    else         v = x[(((size_t)b * T_ + (ls - 1)) * CH_ + ch) * CIN_ + i];
    xcat[idx] = v;
}

__global__ void k_posadd() {
    const size_t idx = (size_t)blockIdx.x * blockDim.x + threadIdx.x;
    if (idx >= (size_t)BE_ * L_ * D_) return;
    const int d = (int)(idx % D_);
    const int l = (int)((idx / D_) % L_);
    const int j = d >> 1;
    const float div = expf(-(float)(2 * j) * (9.210340371976184f / (float)D_));
    const float ang = (float)l * div;
    g_h[idx] += (d & 1) ? cosf(ang) : sinf(ang);
}

// ---------------- batched transpose: (b, Rr, Cc) -> (b, Cc, Rr) with out row stride os ----
__global__ void k_transpose(const float* __restrict__ in, float* __restrict__ out,
                            int Rr, int Cc, int os) {
    __shared__ float tile[32][33];
    const int b  = blockIdx.z;
    const int r0 = blockIdx.y * 32;
    const int c0 = blockIdx.x * 32;
    const int x = threadIdx.x;
    const int y = threadIdx.y;
    #pragma unroll
    for (int yy = y; yy < 32; yy += 8) {
        const int r = r0 + yy, c = c0 + x;
        if (r < Rr && c < Cc) tile[yy][x] = in[((size_t)b * Rr + r) * Cc + c];
    }
    __syncthreads();
    #pragma unroll
    for (int yy = y; yy < 32; yy += 8) {
        const int c = c0 + yy, r = r0 + x;
        if (r < Rr && c < Cc) out[((size_t)b * Cc + c) * os + r] = tile[x][yy];
    }
}

// ---------------- complex frequency mixing, grid (H, M) ----------------
// X: (R x 128) interleaved [Re | Im] per row (row = be*512 + h*64 + i)
// Ainv[row*128 + m] = c_m * Re(S[be,h,o,m]); Ainv[row*128+64+m] = c_m * Im
__global__ void k_mix2(const float* __restrict__ X,
                       const float* __restrict__ fwr, const float* __restrict__ fwi,
                       float* __restrict__ Ainv) {
    const int hh = blockIdx.x;   // 0..7
    const int m  = blockIdx.y;   // 0..63
    const int tid = threadIdx.x; // 256
    __shared__ float sWr[64][64];  // [i][o]
    __shared__ float sWi[64][64];
    __shared__ float sXr[4][64];
    __shared__ float sXi[4][64];
    for (int idx = tid; idx < 4096; idx += 256) {
        const int i = idx >> 6, o = idx & 63;
        const size_t w = (((size_t)hh * 64 + i) * 64 + o) * 64 + m;
        sWr[i][o] = fwr[w];
        sWi[i][o] = fwi[w];
    }
    __syncthreads();
    const int o    = tid & 63;
    const int bloc = tid >> 6;   // 0..3
    const float cm = ((m == 0) ? 1.f : 2.f) / (float)L_;
    for (int be0 = 0; be0 < BE_; be0 += 4) {
        {
            const int i = tid & 63, bl = tid >> 6;
            const size_t xr = ((size_t)(be0 + bl) * D_ + hh * 64 + i) * 128 + m;
            sXr[bl][i] = X[xr];
            sXi[bl][i] = X[xr + 64];
        }
        __syncthreads();
        float ar = 0.f, ai = 0.f;
        #pragma unroll 8
        for (int i = 0; i < 64; ++i) {
            const float xr = sXr[bloc][i], xi = sXi[bloc][i];
            const float wr = sWr[i][o],    wi = sWi[i][o];
            ar += xr * wr - xi * wi;
            ai += xr * wi + xi * wr;
        }
        const size_t row = (size_t)(be0 + bloc) * D_ + hh * 64 + o;
        Ainv[row * 128 + m]      = cm * ar;
        Ainv[row * 128 + 64 + m] = cm * ai;
        __syncthreads();
    }
}

// ---------------- series_decomp residual ----------------
__global__ void k_movmean(float* __restrict__ hbuf) {
    const int be = blockIdx.x;
    const int d0 = blockIdx.y * 32;
    __shared__ float s[L_ * 32];
    const int tid = threadIdx.x;   // 256
    for (int idx = tid; idx < L_ * 32; idx += 256) {
        const int l = idx >> 5, dd = idx & 31;
        s[idx] = hbuf[((size_t)be * L_ + l) * D_ + d0 + dd];
    }
    __syncthreads();
    for (int idx = tid; idx < L_ * 32; idx += 256) {
        const int l = idx >> 5, dd = idx & 31;
        float acc = 0.f;
        #pragma unroll
        for (int j = -12; j <= 12; ++j) {
            int jj = l + j;
            jj = jj < 0 ? 0 : (jj > L_ - 1 ? L_ - 1 : jj);
            acc += s[(jj << 5) + dd];
        }
        hbuf[((size_t)be * L_ + l) * D_ + d0 + dd] = s[idx] - acc * (1.f / 25.f);
    }
}

// ---------------- final LayerNorm over D + mean over L ----------------
__global__ void k_lnpool(const float* __restrict__ g, const float* __restrict__ b) {
    const int be = blockIdx.x;
    const int tid = threadIdx.x;   // 512
    __shared__ float ws[16], ws2[16];
    const int wid = tid >> 5, lane = tid & 31;
    const float gg = g[tid], bb = b[tid];
    float acc = 0.f;
    for (int l = 0; l < L_; ++l) {
        const float v = g_h[((size_t)be * L_ + l) * D_ + tid];
        float s = v, s2 = v * v;
        #pragma unroll
        for (int off = 16; off > 0; off >>= 1) {
            s  += __shfl_xor_sync(0xffffffffu, s, off);
            s2 += __shfl_xor_sync(0xffffffffu, s2, off);
        }
        if (lane == 0) { ws[wid] = s; ws2[wid] = s2; }
        __syncthreads();
        float tot = 0.f, tot2 = 0.f;
        #pragma unroll
        for (int w = 0; w < 16; ++w) { tot += ws[w]; tot2 += ws2[w]; }
        const float mu  = tot * (1.f / (float)D_);
        const float var = tot2 * (1.f / (float)D_) - mu * mu;
        const float inv = rsqrtf(var + 1e-5f);
        acc += (v - mu) * inv * gg + bb;
        __syncthreads();
    }
    g_z[(size_t)be * D_ + tid] = acc * (1.f / (float)L_);
}

// ---------------- decoder layer 1: z2 = gelu(z @ d1w^T + d1b), warp per output ----------
__global__ void k_dec1(const float* __restrict__ w, const float* __restrict__ b1) {
    const int tid = threadIdx.x;
    const int warp = tid >> 5, lane = tid & 31;
    const int idx = blockIdx.x * 8 + warp;   // 0..8191  (= b*512 + o)
    const int bb = idx >> 9;
    const int oo = idx & 511;
    const float* zr = g_z + (size_t)bb * (CH_ * D_);
    const float* wr = w   + (size_t)oo * (CH_ * D_);
    float acc = 0.f;
    for (int k = lane * 4; k < CH_ * D_; k += 128) {
        const float4 zv = *reinterpret_cast<const float4*>(zr + k);
        const float4 wv = *reinterpret_cast<const float4*>(wr + k);
        acc += zv.x * wv.x + zv.y * wv.y + zv.z * wv.z + zv.w * wv.w;
    }
    #pragma unroll
    for (int off = 16; off > 0; off >>= 1) acc += __shfl_xor_sync(0xffffffffu, acc, off);
    if (lane == 0) {
        const float v = acc + b1[oo];
        g_z2[idx] = 0.5f * v * (1.f + erff(v * 0.70710678118654752f));
    }
}

// ---------------- final tiny dot ----------------
__global__ void k_dec2(const float* __restrict__ w, const float* __restrict__ bias,
                       float* __restrict__ out) {
    const int bb = blockIdx.x;
    const int tid = threadIdx.x; // 128
    float acc = 0.f;
    for (int d = tid; d < D_; d += 128) acc += g_z2[bb * D_ + d] * w[d];
    #pragma unroll
    for (int off = 16; off > 0; off >>= 1) acc += __shfl_xor_sync(0xffffffffu, acc, off);
    __shared__ float ws[4];
    if ((tid & 31) == 0) ws[tid >> 5] = acc;
    __syncthreads();
    if (tid == 0) out[bb] = ws[0] + ws[1] + ws[2] + ws[3] + bias[0];
}

// ---------------- orchestration ----------------
extern "C" void kernel_launch(void* const* d_in, const int* in_sizes, int n_in,
                              void* d_out, int out_size) {
    const float* x     = (const float*)d_in[0];
    const float* cls   = (const float*)d_in[3];
    const float* tok_w = (const float*)d_in[4];
    const float* wq    = (const float*)d_in[5];
    const float* bq    = (const float*)d_in[6];
    const float* wo    = (const float*)d_in[7];
    const float* bo    = (const float*)d_in[8];
    const float* c1w   = (const float*)d_in[9];
    const float* c2w   = (const float*)d_in[10];
    const float* fwr   = (const float*)d_in[11];
    const float* fwi   = (const float*)d_in[12];
    const float* ng    = (const float*)d_in[13];
    const float* nb    = (const float*)d_in[14];
    const float* d1w   = (const float*)d_in[15];
    const float* d1b   = (const float*)d_in[16];
    const float* d2w   = (const float*)d_in[17];
    const float* d2b   = (const float*)d_in[18];
    float* out = (float*)d_out;

    float *ph, *pq, *pt, *pxq, *pxqp, *pW2t, *pcs, *pBinv;
    cudaGetSymbolAddress((void**)&ph,    g_h);
    cudaGetSymbolAddress((void**)&pq,    g_q);
    cudaGetSymbolAddress((void**)&pt,    g_t);
    cudaGetSymbolAddress((void**)&pxq,   g_xq);
    cudaGetSymbolAddress((void**)&pxqp,  g_xqp);
    cudaGetSymbolAddress((void**)&pW2t,  g_W2t);
    cudaGetSymbolAddress((void**)&pcs,   g_cs);
    cudaGetSymbolAddress((void**)&pBinv, g_Binv);

    float* pxcat = pq;    // BE*L*K3 fits in g_q
    float* pX    = pq;    // R x 128 (q dead after transpose)
    float* pAinv = pt;    // R x 128 (t free until FFN)

    const dim3 gemmBig(D_ / 128, MR / 128);     // (4, 514)
    const dim3 gemmDft(1, R_ / 128);            // (1, 1024), N=128, K=264
    const dim3 gemmInv((L_ + 127) / 128, R_ / 128); // (3, 1024), N=257, K=128

    // basis tables + pad
    k_init_cs  <<<(128 * LP_ + 255) / 256, 256>>>();
    k_init_binv<<<(L_ * 2 * M_ + 255) / 256, 256>>>();
    k_padzero  <<<(BE_ * D_ * (LP_ - L_) + 255) / 256, 256>>>();

    // embedding
    k_w2t <<<(D_ * K3 + 255) / 256, 256>>>(tok_w);
    k_xcat<<<(int)(((size_t)BE_ * L_ * K3 + 255) / 256), 256>>>(x, cls, pxcat);
    k_gemm128<<<gemmBig, 256>>>(pxcat, pW2t, ph, nullptr, nullptr, D_, K3, 0);
    k_posadd<<<(int)(((size_t)BE_ * L_ * D_ + 255) / 256), 256>>>();

    for (int l = 0; l < NL_; ++l) {
        const float* wql = wq + (size_t)l * D_ * D_;
        const float* bql = bq + (size_t)l * D_;
        const float* wol = wo + (size_t)l * D_ * D_;
        const float* bol = bo + (size_t)l * D_;
        const float* c1l = c1w + (size_t)l * D_ * D_;
        const float* c2l = c2w + (size_t)l * D_ * D_;

        // q = h @ wq^T + bq        (g_q)
        k_gemm128<<<gemmBig, 256>>>(ph, wql, pq, bql, nullptr, D_, D_, 0);
        // xqp[be,d,l] = q[be,l,d]  (padded row stride 264)
        k_transpose<<<dim3(D_ / 32, (L_ + 31) / 32, BE_), dim3(32, 8)>>>(pq, pxqp, L_, D_, LP_);
        // DFT both parts in one GEMM: X (R x 128) = xqp @ [cos; -sin]^T
        k_gemm128<<<gemmDft, 256>>>(pxqp, pcs, pX, nullptr, nullptr, 128, LP_, 0);
        // complex mix -> scaled Ainv
        k_mix2<<<dim3(H_, M_), 256>>>(pX, fwr, fwi, pAinv);
        // inverse rDFT -> (BE, D, L) flat == (BE*L, D) raw reshape
        k_gemm128<<<gemmInv, 256>>>(pAinv, pBinv, pxq, nullptr, nullptr, L_, 2 * M_, 0);
        // h = h + a @ wo^T + bo
        k_gemm128<<<gemmBig, 256>>>(pxq, wol, ph, bol, ph, D_, D_, 1);
        // decomp1
        k_movmean<<<dim3(BE_, D_ / 32), 256>>>(ph);
        // FFN
        k_gemm128<<<gemmBig, 256>>>(ph, c1l, pt, nullptr, nullptr, D_, D_, 2);
        k_gemm128<<<gemmBig, 256>>>(pt, c2l, ph, nullptr, ph, D_, D_, 1);
        // decomp2
        k_movmean<<<dim3(BE_, D_ / 32), 256>>>(ph);
    }

    // LayerNorm + mean-pool -> z; decoders
    k_lnpool<<<BE_, 512>>>(ng, nb);
    k_dec1<<<B_ * D_ / 8, 256>>>(d1w, d1b);
    k_dec2<<<B_, 128>>>(d2w, d2b, out);
}

// round 6
// speedup vs baseline: 2.9565x; 1.1971x over previous
#include <cuda_runtime.h>
#include <cuda_bf16.h>
#include <math.h>
#include <stdint.h>

// ---------------- problem constants ----------------
constexpr int B_   = 16;
constexpr int T_   = 256;
constexpr int CH_  = 16;
constexpr int CIN_ = 64;
constexpr int D_   = 512;
constexpr int H_   = 8;
constexpr int E_   = 64;
constexpr int NL_  = 2;
constexpr int M_   = 64;
constexpr int L_   = T_ + 1; // 257
constexpr int LP_  = 264;
constexpr int BE_  = B_ * CH_;      // 256
constexpr int MR   = BE_ * L_;      // 65792 = 514*128
constexpr int R_   = BE_ * D_;      // 131072
constexpr int K3   = 3 * CIN_;      // 192

// ---------------- scratch ----------------
__device__ float g_h   [(size_t)BE_ * L_ * D_];
__device__ float g_q   [(size_t)BE_ * L_ * D_];
__device__ float g_t   [(size_t)BE_ * L_ * D_];
__device__ float g_xq  [(size_t)BE_ * D_ * L_];
__device__ float g_xqp [(size_t)BE_ * D_ * LP_];
__device__ float g_W2t [(size_t)D_ * K3];
__device__ float g_cs  [128 * LP_];
__device__ float g_Binv[L_ * 2 * M_];
__device__ float g_z  [BE_ * D_];
__device__ float g_z2 [B_ * D_];
__device__ __nv_bfloat16 g_A2[(size_t)MR * 3 * D_];   // split activations [M, 3K] = [hi|lo|hi]
__device__ __nv_bfloat16 g_B2[(size_t)D_ * 3 * D_];   // split weights [512, 3K] = [hi|hi|lo]

// ================= helpers =================
__device__ __forceinline__ uint32_t smem_u32(const void* p) {
    uint32_t a;
    asm("{ .reg .u64 t; cvta.to.shared.u64 t, %1; cvt.u32.u64 %0, t; }" : "=r"(a) : "l"(p));
    return a;
}
__device__ __forceinline__ void ldsm4(uint32_t& r0, uint32_t& r1, uint32_t& r2, uint32_t& r3,
                                      uint32_t a) {
    asm volatile("ldmatrix.sync.aligned.m8n8.x4.shared.b16 {%0,%1,%2,%3}, [%4];"
                 : "=r"(r0), "=r"(r1), "=r"(r2), "=r"(r3) : "r"(a));
}
__device__ __forceinline__ void mma_bf16(float& d0, float& d1, float& d2, float& d3,
                                         uint32_t a0, uint32_t a1, uint32_t a2, uint32_t a3,
                                         uint32_t b0, uint32_t b1) {
    asm volatile("mma.sync.aligned.m16n8k16.row.col.f32.bf16.bf16.f32 "
                 "{%0,%1,%2,%3}, {%4,%5,%6,%7}, {%8,%9}, {%0,%1,%2,%3};"
                 : "+f"(d0), "+f"(d1), "+f"(d2), "+f"(d3)
                 : "r"(a0), "r"(a1), "r"(a2), "r"(a3), "r"(b0), "r"(b1));
}
__device__ __forceinline__ void cp16(uint32_t dst, const void* src) {
    asm volatile("cp.async.cg.shared.global [%0], [%1], 16;"
                 :: "r"(dst), "l"(__cvta_generic_to_global(src)) : "memory");
}

// ========== split: fp32 [rows,K] -> bf16 [rows, 3K] ==========
// amode 0 (activations): [hi | lo | hi]
// amode 1 (weights):     [hi | hi | lo]
// Concatenated-K GEMM then computes Ah*Bh + Al*Bh + Ah*Bl = A*B - Al*Bl (~2^-18 err).
__global__ void k_split(const float* __restrict__ A, __nv_bfloat16* __restrict__ out,
                        int K, int total4, int amode) {
    const int idx = blockIdx.x * blockDim.x + threadIdx.x;
    if (idx >= total4) return;
    const int Kq = K >> 2;
    const int row = idx / Kq;
    const int c   = (idx - row * Kq) << 2;
    const float4 v = *reinterpret_cast<const float4*>(A + (size_t)row * K + c);
    __nv_bfloat16 hi[4], lo[4];
    const float vv[4] = {v.x, v.y, v.z, v.w};
    #pragma unroll
    for (int j = 0; j < 4; ++j) {
        hi[j] = __float2bfloat16_rn(vv[j]);
        lo[j] = __float2bfloat16_rn(vv[j] - __bfloat162float(hi[j]));
    }
    __nv_bfloat16* o = out + (size_t)row * (3 * K);
    const uint2 hv = *reinterpret_cast<uint2*>(hi);
    const uint2 lv = *reinterpret_cast<uint2*>(lo);
    if (amode == 0) {
        *reinterpret_cast<uint2*>(o + c)         = hv;
        *reinterpret_cast<uint2*>(o + K + c)     = lv;
        *reinterpret_cast<uint2*>(o + 2 * K + c) = hv;
    } else {
        *reinterpret_cast<uint2*>(o + c)         = hv;
        *reinterpret_cast<uint2*>(o + K + c)     = hv;
        *reinterpret_cast<uint2*>(o + 2 * K + c) = lv;
    }
}

// ================= bf16 mma.sync GEMM: C[M,512] = A2[M,K2] @ B2[512,K2]^T ==============
// K2 % 64 == 0, M % 128 == 0, N fixed 512 with grid.x == 4.
// mode 0: C = acc + bias ; 1: += res ; 2: gelu(acc + bias)
constexpr int STAGE_BYTES = 2 * 128 * 144;       // 36864
constexpr int SMEM_MMA    = 3 * STAGE_BYTES;     // 110592

__global__ __launch_bounds__(256, 2)
void k_mma(const __nv_bfloat16* __restrict__ A2, const __nv_bfloat16* __restrict__ B2,
           float* __restrict__ C, const float* __restrict__ bias,
           const float* __restrict__ res, int K2, int mode) {
    extern __shared__ char smem[];
    const uint32_t sb = smem_u32(smem);
    const int tid = threadIdx.x;
    const int wid = tid >> 5, lane = tid & 31;
    const int mw = (wid & 1) * 64;
    const int nw = (wid >> 1) * 32;
    const int m0 = blockIdx.y * 128;
    const int n0 = blockIdx.x * 128;

    float acc[4][4][4] = {};

    const int nch = K2 >> 6;

    const int lr = tid >> 1;
    const int lsg = (tid & 1) * 4;
    #define LOAD_STAGE(c, s) do {                                                   \
        const uint32_t base = sb + (s) * STAGE_BYTES;                               \
        const __nv_bfloat16* srcA = A2 + (size_t)(m0 + lr) * K2 + (c) * 64;         \
        const __nv_bfloat16* srcB = B2 + (size_t)(n0 + lr) * K2 + (c) * 64;         \
        _Pragma("unroll")                                                           \
        for (int g = 0; g < 4; ++g) {                                               \
            cp16(base + lr * 144 + (lsg + g) * 16,           srcA + (lsg + g) * 8); \
            cp16(base + 18432 + lr * 144 + (lsg + g) * 16,   srcB + (lsg + g) * 8); \
        }                                                                           \
        asm volatile("cp.async.commit_group;" ::: "memory");                        \
    } while (0)

    LOAD_STAGE(0, 0);
    if (nch > 1) LOAD_STAGE(1, 1);

    const int a_row = mw + (lane & 15);
    const int a_kof = (lane >> 4) * 8;
    const int b_row = nw + ((lane >> 4) << 3) + (lane & 7);
    const int b_kof = ((lane >> 3) & 1) * 8;

    for (int c = 0; c < nch; ++c) {
        if (c + 1 < nch) asm volatile("cp.async.wait_group 1;" ::: "memory");
        else             asm volatile("cp.async.wait_group 0;" ::: "memory");
        __syncthreads();
        if (c + 2 < nch) LOAD_STAGE(c + 2, (c + 2) % 3);

        const uint32_t aB = sb + (c % 3) * STAGE_BYTES;
        const uint32_t bB = aB + 18432;

        #pragma unroll
        for (int ks = 0; ks < 4; ++ks) {
            uint32_t a[4][4];
            #pragma unroll
            for (int mt = 0; mt < 4; ++mt)
                ldsm4(a[mt][0], a[mt][1], a[mt][2], a[mt][3],
                      aB + (a_row + mt * 16) * 144 + (ks * 16 + a_kof) * 2);
            uint32_t b[4][2];
            #pragma unroll
            for (int np = 0; np < 2; ++np)
                ldsm4(b[np * 2][0], b[np * 2][1], b[np * 2 + 1][0], b[np * 2 + 1][1],
                      bB + (b_row + np * 16) * 144 + (ks * 16 + b_kof) * 2);
            #pragma unroll
            for (int mt = 0; mt < 4; ++mt)
                #pragma unroll
                for (int nt = 0; nt < 4; ++nt)
                    mma_bf16(acc[mt][nt][0], acc[mt][nt][1], acc[mt][nt][2], acc[mt][nt][3],
                             a[mt][0], a[mt][1], a[mt][2], a[mt][3],
                             b[nt][0], b[nt][1]);
        }
    }
    #undef LOAD_STAGE

    #pragma unroll
    for (int mt = 0; mt < 4; ++mt) {
        #pragma unroll
        for (int half = 0; half < 2; ++half) {
            const int m = m0 + mw + mt * 16 + (lane >> 2) + half * 8;
            float* Crow = C + (size_t)m * 512;
            const float* Rrow = (mode == 1) ? res + (size_t)m * 512 : nullptr;
            #pragma unroll
            for (int nt = 0; nt < 4; ++nt) {
                const int n = n0 + nw + nt * 8 + (lane & 3) * 2;
                float v0 = acc[mt][nt][half * 2 + 0];
                float v1 = acc[mt][nt][half * 2 + 1];
                if (bias) { v0 += bias[n]; v1 += bias[n + 1]; }
                if (mode == 1) { v0 += Rrow[n]; v1 += Rrow[n + 1]; }
                else if (mode == 2) {
                    v0 = 0.5f * v0 * (1.f + erff(v0 * 0.70710678118654752f));
                    v1 = 0.5f * v1 * (1.f + erff(v1 * 0.70710678118654752f));
                }
                float2 o; o.x = v0; o.y = v1;
                *reinterpret_cast<float2*>(Crow + n) = o;
            }
        }
    }
}

// ================= fp32 GEMM (fourier DFT/inverse) =================
__global__ __launch_bounds__(256, 2)
void k_gemm128(const float* __restrict__ A, const float* __restrict__ Bm,
               float* __restrict__ C, int Nd, int Kd) {
    __shared__ float sA[2][8][128];
    __shared__ float sB[2][8][128];
    const int tid = threadIdx.x;
    const int m0 = blockIdx.y * 128;
    const int n0 = blockIdx.x * 128;
    const int lrow = tid >> 1;
    const int lcol = (tid & 1) * 4;
    const int tx = tid & 15;
    const int ty = tid >> 4;

    const float* Aptr = A + (size_t)(m0 + lrow) * Kd + lcol;
    const bool bvalid = (n0 + lrow) < Nd;
    const float* Bptr = Bm + (size_t)(n0 + lrow) * Kd + lcol;

    float acc[8][8] = {};
    {
        const float4 a = *reinterpret_cast<const float4*>(Aptr);
        float4 b = make_float4(0.f, 0.f, 0.f, 0.f);
        if (bvalid) b = *reinterpret_cast<const float4*>(Bptr);
        sA[0][lcol + 0][lrow] = a.x; sA[0][lcol + 1][lrow] = a.y;
        sA[0][lcol + 2][lrow] = a.z; sA[0][lcol + 3][lrow] = a.w;
        sB[0][lcol + 0][lrow] = b.x; sB[0][lcol + 1][lrow] = b.y;
        sB[0][lcol + 2][lrow] = b.z; sB[0][lcol + 3][lrow] = b.w;
    }
    __syncthreads();
    const int nstages = Kd >> 3;
    int buf = 0;
    #define COMPUTE_STAGE(BUF)                                                     \
        _Pragma("unroll")                                                          \
        for (int k = 0; k < 8; ++k) {                                              \
            const float4 a0 = *reinterpret_cast<const float4*>(&sA[BUF][k][ty * 4]);      \
            const float4 a1 = *reinterpret_cast<const float4*>(&sA[BUF][k][64 + ty * 4]); \
            const float4 b0 = *reinterpret_cast<const float4*>(&sB[BUF][k][tx * 4]);      \
            const float4 b1 = *reinterpret_cast<const float4*>(&sB[BUF][k][64 + tx * 4]); \
            const float av[8] = {a0.x, a0.y, a0.z, a0.w, a1.x, a1.y, a1.z, a1.w};  \
            const float bv[8] = {b0.x, b0.y, b0.z, b0.w, b1.x, b1.y, b1.z, b1.w};  \
            _Pragma("unroll")                                                      \
            for (int i = 0; i < 8; ++i)                                            \
                _Pragma("unroll")                                                  \
                for (int j = 0; j < 8; ++j)                                        \
                    acc[i][j] += av[i] * bv[j];                                    \
        }
    for (int s = 1; s < nstages; ++s) {
        const float4 a = *reinterpret_cast<const float4*>(Aptr + (size_t)s * 8);
        float4 b = make_float4(0.f, 0.f, 0.f, 0.f);
        if (bvalid) b = *reinterpret_cast<const float4*>(Bptr + (size_t)s * 8);
        COMPUTE_STAGE(buf)
        const int nb = buf ^ 1;
        sA[nb][lcol + 0][lrow] = a.x; sA[nb][lcol + 1][lrow] = a.y;
        sA[nb][lcol + 2][lrow] = a.z; sA[nb][lcol + 3][lrow] = a.w;
        sB[nb][lcol + 0][lrow] = b.x; sB[nb][lcol + 1][lrow] = b.y;
        sB[nb][lcol + 2][lrow] = b.z; sB[nb][lcol + 3][lrow] = b.w;
        __syncthreads();
        buf = nb;
    }
    COMPUTE_STAGE(buf)
    #undef COMPUTE_STAGE

    #pragma unroll
    for (int i = 0; i < 8; ++i) {
        const int m = m0 + ((i < 4) ? (ty * 4 + i) : (64 + ty * 4 + i - 4));
        float* Crow = C + (size_t)m * Nd;
        #pragma unroll
        for (int j = 0; j < 8; ++j) {
            const int n = n0 + ((j < 4) ? (tx * 4 + j) : (64 + tx * 4 + j - 4));
            if (n >= Nd) continue;
            Crow[n] = acc[i][j];
        }
    }
}

// ---------------- DFT basis tables ----------------
__global__ void k_init_cs() {
    const int idx = blockIdx.x * blockDim.x + threadIdx.x;
    if (idx >= 128 * LP_) return;
    const int n = idx / LP_;
    const int l = idx % LP_;
    float v = 0.f;
    if (l < L_) {
        const int m = (n < M_) ? n : (n - M_);
        const long r = ((long)m * l) % L_;
        const double ang = 6.283185307179586476925 * (double)r / (double)L_;
        v = (n < M_) ? (float)cos(ang) : (float)(-sin(ang));
    }
    g_cs[idx] = v;
}
__global__ void k_init_binv() {
    const int idx = blockIdx.x * blockDim.x + threadIdx.x;
    if (idx >= L_ * 2 * M_) return;
    const int t = idx / (2 * M_);
    const int k = idx % (2 * M_);
    const int m = (k < M_) ? k : (k - M_);
    const long r = ((long)t * m) % L_;
    const double ang = 6.283185307179586476925 * (double)r / (double)L_;
    g_Binv[idx] = (k < M_) ? (float)cos(ang) : (float)(-sin(ang));
}
__global__ void k_padzero() {
    const int idx = blockIdx.x * blockDim.x + threadIdx.x;
    const int nrows = BE_ * D_;
    if (idx >= nrows * (LP_ - L_)) return;
    const int row = idx / (LP_ - L_);
    const int c   = idx % (LP_ - L_);
    g_xqp[(size_t)row * LP_ + L_ + c] = 0.f;
}

// ---------------- token embedding prep ----------------
__global__ void k_w2t(const float* __restrict__ tok_w) {
    const int idx = blockIdx.x * blockDim.x + threadIdx.x;
    if (idx >= D_ * K3) return;
    const int o = idx / K3;
    const int c = idx % K3;
    const int k = c / CIN_;
    const int i = c % CIN_;
    g_W2t[idx] = tok_w[(o * CIN_ + i) * 3 + k];
}
__global__ void k_xcat(const float* __restrict__ x, const float* __restrict__ cls,
                       float* __restrict__ xcat) {
    const size_t idx = (size_t)blockIdx.x * blockDim.x + threadIdx.x;
    if (idx >= (size_t)BE_ * L_ * K3) return;
    const int c  = (int)(idx % K3);
    const int l  = (int)((idx / K3) % L_);
    const int be = (int)(idx / ((size_t)K3 * L_));
    const int k = c / CIN_;
    const int i = c % CIN_;
    const int ls = (l + k - 1 + L_) % L_;
    const int b  = be / CH_;
    const int ch = be % CH_;
    float v;
    if (ls == 0) v = cls[ch * CIN_ + i];
    else         v = x[(((size_t)b * T_ + (ls - 1)) * CH_ + ch) * CIN_ + i];
    xcat[idx] = v;
}
__global__ void k_posadd() {
    const size_t idx = (size_t)blockIdx.x * blockDim.x + threadIdx.x;
    if (idx >= (size_t)BE_ * L_ * D_) return;
    const int d = (int)(idx % D_);
    const int l = (int)((idx / D_) % L_);
    const int j = d >> 1;
    const float div = expf(-(float)(2 * j) * (9.210340371976184f / (float)D_));
    const float ang = (float)l * div;
    g_h[idx] += (d & 1) ? cosf(ang) : sinf(ang);
}

// ---------------- batched transpose ----------------
__global__ void k_transpose(const float* __restrict__ in, float* __restrict__ out,
                            int Rr, int Cc, int os) {
    __shared__ float tile[32][33];
    const int b  = blockIdx.z;
    const int r0 = blockIdx.y * 32;
    const int c0 = blockIdx.x * 32;
    const int x = threadIdx.x;
    const int y = threadIdx.y;
    #pragma unroll
    for (int yy = y; yy < 32; yy += 8) {
        const int r = r0 + yy, c = c0 + x;
        if (r < Rr && c < Cc) tile[yy][x] = in[((size_t)b * Rr + r) * Cc + c];
    }
    __syncthreads();
    #pragma unroll
    for (int yy = y; yy < 32; yy += 8) {
        const int c = c0 + yy, r = r0 + x;
        if (r < Rr && c < Cc) out[((size_t)b * Cc + c) * os + r] = tile[x][yy];
    }
}

// ---------------- complex frequency mixing ----------------
__global__ void k_mix2(const float* __restrict__ X,
                       const float* __restrict__ fwr, const float* __restrict__ fwi,
                       float* __restrict__ Ainv) {
    const int hh = blockIdx.x;
    const int m  = blockIdx.y;
    const int tid = threadIdx.x;
    __shared__ float sWr[64][64];
    __shared__ float sWi[64][64];
    __shared__ float sXr[4][64];
    __shared__ float sXi[4][64];
    for (int idx = tid; idx < 4096; idx += 256) {
        const int i = idx >> 6, o = idx & 63;
        const size_t w = (((size_t)hh * 64 + i) * 64 + o) * 64 + m;
        sWr[i][o] = fwr[w];
        sWi[i][o] = fwi[w];
    }
    __syncthreads();
    const int o    = tid & 63;
    const int bloc = tid >> 6;
    const float cm = ((m == 0) ? 1.f : 2.f) / (float)L_;
    for (int be0 = 0; be0 < BE_; be0 += 4) {
        {
            const int i = tid & 63, bl = tid >> 6;
            const size_t xr = ((size_t)(be0 + bl) * D_ + hh * 64 + i) * 128 + m;
            sXr[bl][i] = X[xr];
            sXi[bl][i] = X[xr + 64];
        }
        __syncthreads();
        float ar = 0.f, ai = 0.f;
        #pragma unroll 8
        for (int i = 0; i < 64; ++i) {
            const float xr = sXr[bloc][i], xi = sXi[bloc][i];
            const float wr = sWr[i][o],    wi = sWi[i][o];
            ar += xr * wr - xi * wi;
            ai += xr * wi + xi * wr;
        }
        const size_t row = (size_t)(be0 + bloc) * D_ + hh * 64 + o;
        Ainv[row * 128 + m]      = cm * ar;
        Ainv[row * 128 + 64 + m] = cm * ai;
        __syncthreads();
    }
}

// ---------------- series_decomp residual ----------------
__global__ void k_movmean(float* __restrict__ hbuf) {
    const int be = blockIdx.x;
    const int d0 = blockIdx.y * 32;
    __shared__ float s[L_ * 32];
    const int tid = threadIdx.x;
    for (int idx = tid; idx < L_ * 32; idx += 256) {
        const int l = idx >> 5, dd = idx & 31;
        s[idx] = hbuf[((size_t)be * L_ + l) * D_ + d0 + dd];
    }
    __syncthreads();
    for (int idx = tid; idx < L_ * 32; idx += 256) {
        const int l = idx >> 5, dd = idx & 31;
        float acc = 0.f;
        #pragma unroll
        for (int j = -12; j <= 12; ++j) {
            int jj = l + j;
            jj = jj < 0 ? 0 : (jj > L_ - 1 ? L_ - 1 : jj);
            acc += s[(jj << 5) + dd];
        }
        hbuf[((size_t)be * L_ + l) * D_ + d0 + dd] = s[idx] - acc * (1.f / 25.f);
    }
}

// ---------------- final LayerNorm + mean-pool ----------------
__global__ void k_lnpool(const float* __restrict__ g, const float* __restrict__ b) {
    const int be = blockIdx.x;
    const int tid = threadIdx.x;
    __shared__ float ws[16], ws2[16];
    const int wid = tid >> 5, lane = tid & 31;
    const float gg = g[tid], bb = b[tid];
    float acc = 0.f;
    for (int l = 0; l < L_; ++l) {
        const float v = g_h[((size_t)be * L_ + l) * D_ + tid];
        float s = v, s2 = v * v;
        #pragma unroll
        for (int off = 16; off > 0; off >>= 1) {
            s  += __shfl_xor_sync(0xffffffffu, s, off);
            s2 += __shfl_xor_sync(0xffffffffu, s2, off);
        }
        if (lane == 0) { ws[wid] = s; ws2[wid] = s2; }
        __syncthreads();
        float tot = 0.f, tot2 = 0.f;
        #pragma unroll
        for (int w = 0; w < 16; ++w) { tot += ws[w]; tot2 += ws2[w]; }
        const float mu  = tot * (1.f / (float)D_);
        const float var = tot2 * (1.f / (float)D_) - mu * mu;
        const float inv = rsqrtf(var + 1e-5f);
        acc += (v - mu) * inv * gg + bb;
        __syncthreads();
    }
    g_z[(size_t)be * D_ + tid] = acc * (1.f / (float)L_);
}

// ---------------- decoders ----------------
__global__ void k_dec1(const float* __restrict__ w, const float* __restrict__ b1) {
    const int tid = threadIdx.x;
    const int warp = tid >> 5, lane = tid & 31;
    const int idx = blockIdx.x * 8 + warp;
    const int bb = idx >> 9;
    const int oo = idx & 511;
    const float* zr = g_z + (size_t)bb * (CH_ * D_);
    const float* wr = w   + (size_t)oo * (CH_ * D_);
    float acc = 0.f;
    for (int k = lane * 4; k < CH_ * D_; k += 128) {
        const float4 zv = *reinterpret_cast<const float4*>(zr + k);
        const float4 wv = *reinterpret_cast<const float4*>(wr + k);
        acc += zv.x * wv.x + zv.y * wv.y + zv.z * wv.z + zv.w * wv.w;
    }
    #pragma unroll
    for (int off = 16; off > 0; off >>= 1) acc += __shfl_xor_sync(0xffffffffu, acc, off);
    if (lane == 0) {
        const float v = acc + b1[oo];
        g_z2[idx] = 0.5f * v * (1.f + erff(v * 0.70710678118654752f));
    }
}
__global__ void k_dec2(const float* __restrict__ w, const float* __restrict__ bias,
                       float* __restrict__ out) {
    const int bb = blockIdx.x;
    const int tid = threadIdx.x;
    float acc = 0.f;
    for (int d = tid; d < D_; d += 128) acc += g_z2[bb * D_ + d] * w[d];
    #pragma unroll
    for (int off = 16; off > 0; off >>= 1) acc += __shfl_xor_sync(0xffffffffu, acc, off);
    __shared__ float ws[4];
    if ((tid & 31) == 0) ws[tid >> 5] = acc;
    __syncthreads();
    if (tid == 0) out[bb] = ws[0] + ws[1] + ws[2] + ws[3] + bias[0];
}

// ---------------- orchestration ----------------
extern "C" void kernel_launch(void* const* d_in, const int* in_sizes, int n_in,
                              void* d_out, int out_size) {
    const float* x     = (const float*)d_in[0];
    const float* cls   = (const float*)d_in[3];
    const float* tok_w = (const float*)d_in[4];
    const float* wq    = (const float*)d_in[5];
    const float* bq    = (const float*)d_in[6];
    const float* wo    = (const float*)d_in[7];
    const float* bo    = (const float*)d_in[8];
    const float* c1w   = (const float*)d_in[9];
    const float* c2w   = (const float*)d_in[10];
    const float* fwr   = (const float*)d_in[11];
    const float* fwi   = (const float*)d_in[12];
    const float* ng    = (const float*)d_in[13];
    const float* nb    = (const float*)d_in[14];
    const float* d1w   = (const float*)d_in[15];
    const float* d1b   = (const float*)d_in[16];
    const float* d2w   = (const float*)d_in[17];
    const float* d2b   = (const float*)d_in[18];
    float* out = (float*)d_out;

    float *ph, *pq, *pt, *pxq, *pxqp, *pW2t, *pcs, *pBinv;
    __nv_bfloat16 *pA2, *pB2;
    cudaGetSymbolAddress((void**)&ph,    g_h);
    cudaGetSymbolAddress((void**)&pq,    g_q);
    cudaGetSymbolAddress((void**)&pt,    g_t);
    cudaGetSymbolAddress((void**)&pxq,   g_xq);
    cudaGetSymbolAddress((void**)&pxqp,  g_xqp);
    cudaGetSymbolAddress((void**)&pW2t,  g_W2t);
    cudaGetSymbolAddress((void**)&pcs,   g_cs);
    cudaGetSymbolAddress((void**)&pBinv, g_Binv);
    cudaGetSymbolAddress((void**)&pA2,   g_A2);
    cudaGetSymbolAddress((void**)&pB2,   g_B2);

    float* pxcat = pq;
    float* pX    = pq;
    float* pAinv = pt;

    cudaFuncSetAttribute(k_mma, cudaFuncAttributeMaxDynamicSharedMemorySize, SMEM_MMA);

    const dim3 gTC(4, MR / 128);                    // bf16 mma N=512 GEMMs
    const dim3 gemmDft(1, R_ / 128);                // fp32, N=128, K=264
    const dim3 gemmInv((L_ + 127) / 128, R_ / 128); // fp32, N=257, K=128
    const int splitAblk  = (MR * D_ / 4 + 255) / 256;
    const int splitA3blk = (MR * K3 / 4 + 255) / 256;
    const int splitWblk  = (D_ * D_ / 4 + 255) / 256;
    const int splitW3blk = (D_ * K3 / 4 + 255) / 256;

    // tables
    k_init_cs  <<<(128 * LP_ + 255) / 256, 256>>>();
    k_init_binv<<<(L_ * 2 * M_ + 255) / 256, 256>>>();
    k_padzero  <<<(BE_ * D_ * (LP_ - L_) + 255) / 256, 256>>>();

    // embedding (bf16 split GEMM, K2 = 3*192 = 576)
    k_w2t <<<(D_ * K3 + 255) / 256, 256>>>(tok_w);
    k_xcat<<<(int)(((size_t)BE_ * L_ * K3 + 255) / 256), 256>>>(x, cls, pxcat);
    k_split<<<splitA3blk, 256>>>(pxcat, pA2, K3, MR * K3 / 4, 0);
    k_split<<<splitW3blk, 256>>>(pW2t, pB2, K3, D_ * K3 / 4, 1);
    k_mma<<<gTC, 256, SMEM_MMA>>>(pA2, pB2, ph, nullptr, nullptr, 3 * K3, 0);
    k_posadd<<<(int)(((size_t)BE_ * L_ * D_ + 255) / 256), 256>>>();

    for (int l = 0; l < NL_; ++l) {
        const float* wql = wq + (size_t)l * D_ * D_;
        const float* bql = bq + (size_t)l * D_;
        const float* wol = wo + (size_t)l * D_ * D_;
        const float* bol = bo + (size_t)l * D_;
        const float* c1l = c1w + (size_t)l * D_ * D_;
        const float* c2l = c2w + (size_t)l * D_ * D_;

        // q = h @ wq^T + bq
        k_split<<<splitAblk, 256>>>(ph, pA2, D_, MR * D_ / 4, 0);
        k_split<<<splitWblk, 256>>>(wql, pB2, D_, D_ * D_ / 4, 1);
        k_mma<<<gTC, 256, SMEM_MMA>>>(pA2, pB2, pq, bql, nullptr, 3 * D_, 0);
        // transpose -> padded xq
        k_transpose<<<dim3(D_ / 32, (L_ + 31) / 32, BE_), dim3(32, 8)>>>(pq, pxqp, L_, D_, LP_);
        // DFT (fp32)
        k_gemm128<<<gemmDft, 256>>>(pxqp, pcs, pX, 128, LP_);
        // mix -> Ainv
        k_mix2<<<dim3(H_, M_), 256>>>(pX, fwr, fwi, pAinv);
        // inverse DFT (fp32) -> (BE*L, D) via raw reshape
        k_gemm128<<<gemmInv, 256>>>(pAinv, pBinv, pxq, 257, 2 * M_);
        // h = h + a @ wo^T + bo
        k_split<<<splitAblk, 256>>>(pxq, pA2, D_, MR * D_ / 4, 0);
        k_split<<<splitWblk, 256>>>(wol, pB2, D_, D_ * D_ / 4, 1);
        k_mma<<<gTC, 256, SMEM_MMA>>>(pA2, pB2, ph, bol, ph, 3 * D_, 1);
        k_movmean<<<dim3(BE_, D_ / 32), 256>>>(ph);
        // FFN
        k_split<<<splitAblk, 256>>>(ph, pA2, D_, MR * D_ / 4, 0);
        k_split<<<splitWblk, 256>>>(c1l, pB2, D_, D_ * D_ / 4, 1);
        k_mma<<<gTC, 256, SMEM_MMA>>>(pA2, pB2, pt, nullptr, nullptr, 3 * D_, 2);
        k_split<<<splitAblk, 256>>>(pt, pA2, D_, MR * D_ / 4, 0);
        k_split<<<splitWblk, 256>>>(c2l, pB2, D_, D_ * D_ / 4, 1);
        k_mma<<<gTC, 256, SMEM_MMA>>>(pA2, pB2, ph, nullptr, ph, 3 * D_, 1);
        k_movmean<<<dim3(BE_, D_ / 32), 256>>>(ph);
    }

    k_lnpool<<<BE_, 512>>>(ng, nb);
    k_dec1<<<B_ * D_ / 8, 256>>>(d1w, d1b);
    k_dec2<<<B_, 128>>>(d2w, d2b, out);
}